// round 14
// baseline (speedup 1.0000x reference)
#include <cuda_runtime.h>
#include <cuda_fp16.h>
#include <cstdint>

#define BAGS 16
#define NN   5000
#define EE   160000
#define DE   256
#define DIN  128

// ---------------- scratch (device globals) -----------------------------------
__device__ __align__(16) __half g_x [BAGS*NN*DIN];
__device__ __align__(16) __half g_h [BAGS*NN*DE];     // h, later g1
__device__ __align__(16) __half g_u [BAGS*NN*DE];     // u (gathered, fp16)
__device__ __align__(16) __half g_v [BAGS*NN*DE];
__device__ float g_emb[BAGS*DE];
// transposed fp16 weights: Wt[n][k] = W[k][n]
__device__ __align__(16) __half g_we[DE*DIN];
__device__ __align__(16) __half g_w1[DE*DE], g_w2[DE*DE], g_w3[DE*DE], g_w4[DE*DE];
// CSR
__device__ int g_deg[BAGS*NN], g_rowptr[BAGS*(NN+1)], g_cursor[BAGS*NN], g_col[BAGS*EE];

// ---------------- helpers -----------------------------------------------------
__device__ __forceinline__ uint32_t smem_u32(const void* p) {
    uint32_t a;
    asm("{ .reg .u64 t; cvta.to.shared.u64 t, %1; cvt.u32.u64 %0, t; }" : "=r"(a) : "l"(p));
    return a;
}
__device__ __forceinline__ uint32_t pack_h2(float v0, float v1) {
    __half2 h = __floats2half2_rn(v0, v1);
    return *reinterpret_cast<uint32_t*>(&h);
}
template <int S> __device__ __forceinline__ const __half* wsel() {
    switch (S) {
        case 0:  return g_we;
        case 1:  return g_w1;
        case 2:  return g_w2;
        case 3:  return g_w3;
        default: return g_w4;
    }
}

// ---------------- prep --------------------------------------------------------
__global__ void k_zero() {
    int i = blockIdx.x * blockDim.x + threadIdx.x;
    if (i < BAGS * NN) g_deg[i] = 0;
    if (i < BAGS * DE) g_emb[i] = 0.f;
}
#define P_DEG (BAGS*EE)
#define P_X   (BAGS*NN*DIN)
#define P_WE  (DE*DIN)
#define P_W4  (4*DE*DE)
#define P_TOT (P_DEG + P_X + P_WE + P_W4)
// one flat kernel: edge-degree histogram + all fp32->fp16 conversions
__global__ void k_prep(const float* __restrict__ x, const int* __restrict__ ei,
                       const float* __restrict__ We, const float* __restrict__ W1,
                       const float* __restrict__ W2, const float* __restrict__ W3,
                       const float* __restrict__ W4) {
    int idx = blockIdx.x * blockDim.x + threadIdx.x;
    if (idx < P_DEG) {
        int b = idx / EE, e = idx - b * EE;
        int dst = ei[(size_t)b * 2 * EE + EE + e];
        if ((unsigned)dst < NN) atomicAdd(&g_deg[b * NN + dst], 1);
        return;
    }
    idx -= P_DEG;
    if (idx < P_X) { g_x[idx] = __float2half_rn(x[idx]); return; }
    idx -= P_X;
    if (idx < P_WE) {
        int n = idx >> 7, k = idx & 127;
        g_we[idx] = __float2half_rn(We[k * DE + n]);
        return;
    }
    idx -= P_WE;
    if (idx < P_W4) {
        int w = idx >> 16, j = idx & 65535;
        const float* W = (w == 0) ? W1 : (w == 1) ? W2 : (w == 2) ? W3 : W4;
        __half* O = (w == 0) ? g_w1 : (w == 1) ? g_w2 : (w == 2) ? g_w3 : g_w4;
        int n = j >> 8, k = j & 255;
        O[j] = __float2half_rn(W[k * DE + n]);
    }
}

// ---------------- CSR scan + fill ---------------------------------------------
__global__ void k_scan() {
    int b = blockIdx.x, t = threadIdx.x;
    __shared__ int sh[1024];
    int carry = 0;
    for (int c = 0; c < 5; c++) {
        int idx = c * 1024 + t;
        int v = (idx < NN) ? g_deg[b * NN + idx] : 0;
        sh[t] = v;
        __syncthreads();
        for (int off = 1; off < 1024; off <<= 1) {
            int add = (t >= off) ? sh[t - off] : 0;
            __syncthreads();
            sh[t] += add;
            __syncthreads();
        }
        int excl = sh[t] - v;
        if (idx < NN) {
            g_rowptr[b * (NN + 1) + idx] = carry + excl;
            g_cursor[b * NN + idx] = carry + excl;
        }
        int tot = sh[1023];
        __syncthreads();
        carry += tot;
    }
    if (t == 0) g_rowptr[b * (NN + 1) + NN] = carry;
}
__global__ void k_fill(const int* __restrict__ ei) {
    int e = blockIdx.x * blockDim.x + threadIdx.x;
    int b = blockIdx.y;
    if (e >= EE) return;
    int src = ei[(size_t)b * 2 * EE + e];
    int dst = ei[(size_t)b * 2 * EE + EE + e];
    if ((unsigned)dst >= NN || (unsigned)src >= NN) return;
    int p = atomicAdd(&g_cursor[b * NN + dst], 1);
    g_col[b * EE + p] = src;
}

// ---------------- GEMM machinery ----------------------------------------------
#define PITCH 80

__device__ __forceinline__ void issue_chunk(
    const __half* __restrict__ Agl, const __half* __restrict__ Bgl,
    int KD, int m0, int kc, char* sA, char* sB, int tid)
{
    #pragma unroll
    for (int v = 0; v < 2; v++) {
        int idx = v * 256 + tid;
        int row = idx >> 2, c16 = idx & 3;
        int gr = m0 + row;
        const void* src = Agl + (size_t)gr * KD + kc + c16 * 8;
        uint32_t dst = smem_u32(sA + row * PITCH + c16 * 16);
        int sz = (gr < NN) ? 16 : 0;
        asm volatile("cp.async.cg.shared.global [%0], [%1], 16, %2;"
                     :: "r"(dst), "l"(src), "r"(sz));
    }
    #pragma unroll
    for (int v = 0; v < 2; v++) {
        int idx = v * 256 + tid;
        int row = idx >> 2, c16 = idx & 3;
        const void* src = Bgl + (size_t)row * KD + kc + c16 * 8;
        uint32_t dst = smem_u32(sB + row * PITCH + c16 * 16);
        asm volatile("cp.async.cg.shared.global [%0], [%1], 16;"
                     :: "r"(dst), "l"(src));
    }
    asm volatile("cp.async.commit_group;");
}

__device__ __forceinline__ void mma_chunk(const char* sA, const char* sB,
                                          int wm, int wn, int lane, float acc[4][4][4]) {
    #pragma unroll
    for (int ks = 0; ks < 2; ks++) {
        uint32_t afr[4][4];
        #pragma unroll
        for (int mi = 0; mi < 4; mi++) {
            uint32_t ad = smem_u32(sA + (wm * 64 + mi * 16 + (lane & 15)) * PITCH
                                      + ks * 32 + (lane >> 4) * 16);
            asm volatile("ldmatrix.sync.aligned.m8n8.x4.shared.b16 {%0,%1,%2,%3}, [%4];"
                         : "=r"(afr[mi][0]), "=r"(afr[mi][1]),
                           "=r"(afr[mi][2]), "=r"(afr[mi][3]) : "r"(ad));
        }
        uint32_t bfr[4][2];
        #pragma unroll
        for (int q = 0; q < 2; q++) {
            int g = lane >> 3;
            uint32_t bd = smem_u32(sB + (wn * 32 + q * 16 + (g >> 1) * 8 + (lane & 7)) * PITCH
                                      + ks * 32 + (g & 1) * 16);
            asm volatile("ldmatrix.sync.aligned.m8n8.x4.shared.b16 {%0,%1,%2,%3}, [%4];"
                         : "=r"(bfr[2 * q][0]), "=r"(bfr[2 * q][1]),
                           "=r"(bfr[2 * q + 1][0]), "=r"(bfr[2 * q + 1][1]) : "r"(bd));
        }
        #pragma unroll
        for (int mi = 0; mi < 4; mi++)
            #pragma unroll
            for (int ni = 0; ni < 4; ni++)
                asm volatile(
                    "mma.sync.aligned.m16n8k16.row.col.f32.f16.f16.f32 "
                    "{%0,%1,%2,%3}, {%4,%5,%6,%7}, {%8,%9}, {%0,%1,%2,%3};"
                    : "+f"(acc[mi][ni][0]), "+f"(acc[mi][ni][1]),
                      "+f"(acc[mi][ni][2]), "+f"(acc[mi][ni][3])
                    : "r"(afr[mi][0]), "r"(afr[mi][1]), "r"(afr[mi][2]), "r"(afr[mi][3]),
                      "r"(bfr[ni][0]), "r"(bfr[ni][1]));
    }
}

// ---------------- encoder: h = relu(x@We + be) -> fp16 ------------------------
__global__ void __launch_bounds__(256, 2) k_enc(const float* __restrict__ bias) {
    __shared__ __align__(16) char smA[2][128 * PITCH];
    __shared__ __align__(16) char smB[2][128 * PITCH];
    const int KD = DIN;
    int tid = threadIdx.x, lane = tid & 31, warp = tid >> 5;
    int wm = warp & 1, wn = warp >> 1;
    int m0 = blockIdx.x * 128, n0 = blockIdx.y * 128, b = blockIdx.z;

    const __half* Ah = g_x + (size_t)b * NN * KD;
    const __half* Bh = g_we + (size_t)n0 * KD;

    const int TOT = KD / 32;
    float acc[4][4][4] = {};
    issue_chunk(Ah, Bh, KD, m0, 0, smA[0], smB[0], tid);
    issue_chunk(Ah, Bh, KD, m0, 32, smA[1], smB[1], tid);
    for (int it = 0; it < TOT; it++) {
        if (it + 1 < TOT) asm volatile("cp.async.wait_group 1;");
        else              asm volatile("cp.async.wait_group 0;");
        __syncthreads();
        mma_chunk(smA[it & 1], smB[it & 1], wm, wn, lane, acc);
        __syncthreads();
        if (it + 2 < TOT)
            issue_chunk(Ah, Bh, KD, m0, (it + 2) * 32, smA[it & 1], smB[it & 1], tid);
    }

    #pragma unroll
    for (int mi = 0; mi < 4; mi++)
        #pragma unroll
        for (int ni = 0; ni < 4; ni++) {
            int r0 = m0 + wm * 64 + mi * 16 + (lane >> 2);
            int c0 = n0 + wn * 32 + ni * 8 + (lane & 3) * 2;
            float b0 = __ldg(&bias[c0]), b1 = __ldg(&bias[c0 + 1]);
            float v00 = fmaxf(acc[mi][ni][0] + b0, 0.f), v01 = fmaxf(acc[mi][ni][1] + b1, 0.f);
            float v10 = fmaxf(acc[mi][ni][2] + b0, 0.f), v11 = fmaxf(acc[mi][ni][3] + b1, 0.f);
            if (r0 < NN)
                *(uint32_t*)&g_h[((size_t)b * NN + r0) * DE + c0] = pack_h2(v00, v01);
            if (r0 + 8 < NN)
                *(uint32_t*)&g_h[((size_t)b * NN + r0 + 8) * DE + c0] = pack_h2(v10, v11);
        }
}

// ---------------- layer GEMM: u = h@Wl (fp16), v = h@Wr + bias (fp16) ---------
template <int WLSEL, int WRSEL>
__global__ void __launch_bounds__(256, 2) k_layer(const float* __restrict__ bias) {
    __shared__ __align__(16) char smA[2][128 * PITCH];
    __shared__ __align__(16) char smB[2][128 * PITCH];
    const int KD = DE;
    int tid = threadIdx.x, lane = tid & 31, warp = tid >> 5;
    int wm = warp & 1, wn = warp >> 1;
    int m0 = blockIdx.x * 128, n0 = blockIdx.y * 128, b = blockIdx.z;

    const __half* Ah = g_h + (size_t)b * NN * KD;
    const __half* WL = wsel<WLSEL>() + (size_t)n0 * KD;
    const __half* WR = wsel<WRSEL>() + (size_t)n0 * KD;

    const int NCH = KD / 32, TOT = 2 * NCH;
    float acc[4][4][4] = {};
    #define BPL(it) ((it) < NCH ? WL : WR)
    issue_chunk(Ah, BPL(0), KD, m0, 0, smA[0], smB[0], tid);
    issue_chunk(Ah, BPL(1), KD, m0, (1 % NCH) * 32, smA[1], smB[1], tid);
    for (int it = 0; it < TOT; it++) {
        if (it + 1 < TOT) asm volatile("cp.async.wait_group 1;");
        else              asm volatile("cp.async.wait_group 0;");
        __syncthreads();
        mma_chunk(smA[it & 1], smB[it & 1], wm, wn, lane, acc);
        __syncthreads();
        if (it + 2 < TOT)
            issue_chunk(Ah, BPL(it + 2), KD, m0, ((it + 2) % NCH) * 32,
                        smA[it & 1], smB[it & 1], tid);
        if (it == NCH - 1) {
            // u complete: write fp16, reset accumulators
            #pragma unroll
            for (int mi = 0; mi < 4; mi++)
                #pragma unroll
                for (int ni = 0; ni < 4; ni++) {
                    int r0 = m0 + wm * 64 + mi * 16 + (lane >> 2);
                    int c0 = n0 + wn * 32 + ni * 8 + (lane & 3) * 2;
                    if (r0 < NN)
                        *(uint32_t*)&g_u[((size_t)b * NN + r0) * DE + c0] =
                            pack_h2(acc[mi][ni][0], acc[mi][ni][1]);
                    if (r0 + 8 < NN)
                        *(uint32_t*)&g_u[((size_t)b * NN + r0 + 8) * DE + c0] =
                            pack_h2(acc[mi][ni][2], acc[mi][ni][3]);
                    acc[mi][ni][0] = acc[mi][ni][1] = acc[mi][ni][2] = acc[mi][ni][3] = 0.f;
                }
        }
    }
    #undef BPL

    // v epilogue (+bias, fp16)
    #pragma unroll
    for (int mi = 0; mi < 4; mi++)
        #pragma unroll
        for (int ni = 0; ni < 4; ni++) {
            int r0 = m0 + wm * 64 + mi * 16 + (lane >> 2);
            int c0 = n0 + wn * 32 + ni * 8 + (lane & 3) * 2;
            float b0 = __ldg(&bias[c0]), b1 = __ldg(&bias[c0 + 1]);
            if (r0 < NN)
                *(uint32_t*)&g_v[((size_t)b * NN + r0) * DE + c0] =
                    pack_h2(acc[mi][ni][0] + b0, acc[mi][ni][1] + b1);
            if (r0 + 8 < NN)
                *(uint32_t*)&g_v[((size_t)b * NN + r0 + 8) * DE + c0] =
                    pack_h2(acc[mi][ni][2] + b0, acc[mi][ni][3] + b1);
        }
}

// ---------------- fused SAGE combine: g = relu(mean_e(U) + V) -----------------
// FINAL=false: write fp16 g1 into g_h.  FINAL=true: atomic-reduce into g_emb.
template <bool FINAL>
__global__ void k_agg2() {
    int w = (blockIdx.x * blockDim.x + threadIdx.x) >> 5;
    int lane = threadIdx.x & 31;
    if (w >= BAGS * NN) return;
    int b = w / NN, i = w - b * NN;
    int r0 = g_rowptr[b * (NN + 1) + i];
    int r1 = g_rowptr[b * (NN + 1) + i + 1];
    const __half* Ub = g_u + (size_t)b * NN * DE;
    const int* colb = g_col + b * EE;
    __half2 a0 = __floats2half2_rn(0.f, 0.f), a1 = a0, a2 = a0, a3 = a0;
    for (int e = r0; e < r1; e++) {
        int s = __ldg(&colb[e]);
        uint4 r = __ldg((const uint4*)(Ub + (size_t)s * DE) + lane);
        a0 = __hadd2(a0, *reinterpret_cast<__half2*>(&r.x));
        a1 = __hadd2(a1, *reinterpret_cast<__half2*>(&r.y));
        a2 = __hadd2(a2, *reinterpret_cast<__half2*>(&r.z));
        a3 = __hadd2(a3, *reinterpret_cast<__half2*>(&r.w));
    }
    int dg = r1 - r0;
    float inv = 1.f / (float)(dg > 1 ? dg : 1);
    size_t base = ((size_t)b * NN + i) * DE + lane * 8;
    uint4 rv = *(const uint4*)(g_v + base);
    float2 f0 = __half22float2(a0), f1 = __half22float2(a1);
    float2 f2 = __half22float2(a2), f3 = __half22float2(a3);
    float2 v0 = __half22float2(*reinterpret_cast<__half2*>(&rv.x));
    float2 v1 = __half22float2(*reinterpret_cast<__half2*>(&rv.y));
    float2 v2 = __half22float2(*reinterpret_cast<__half2*>(&rv.z));
    float2 v3 = __half22float2(*reinterpret_cast<__half2*>(&rv.w));
    float g[8];
    g[0] = fmaxf(f0.x * inv + v0.x, 0.f); g[1] = fmaxf(f0.y * inv + v0.y, 0.f);
    g[2] = fmaxf(f1.x * inv + v1.x, 0.f); g[3] = fmaxf(f1.y * inv + v1.y, 0.f);
    g[4] = fmaxf(f2.x * inv + v2.x, 0.f); g[5] = fmaxf(f2.y * inv + v2.y, 0.f);
    g[6] = fmaxf(f3.x * inv + v3.x, 0.f); g[7] = fmaxf(f3.y * inv + v3.y, 0.f);
    if (!FINAL) {
        uint32_t hp[4];
        #pragma unroll
        for (int q = 0; q < 4; q++) hp[q] = pack_h2(g[2 * q], g[2 * q + 1]);
        *(uint4*)(&g_h[base]) = *(uint4*)hp;
    } else {
        // pooled embedding: emb[b][c] += g2[b][i][c]  (softmax over 1 cluster == 1)
        float* eb = g_emb + b * DE + lane * 8;
        #pragma unroll
        for (int q = 0; q < 8; q++) atomicAdd(&eb[q], g[q]);
    }
}

// ---------------- classifier --------------------------------------------------
__global__ void k_cls(const float* __restrict__ Wc1, const float* __restrict__ bc1,
                      const float* __restrict__ Wc2, const float* __restrict__ bc2,
                      float* __restrict__ out) {
    int b = blockIdx.x, t = threadIdx.x;   // 128 threads
    __shared__ float es[256];
    __shared__ float r0[128], r1[128];
    es[t]       = g_emb[b * DE + t];
    es[t + 128] = g_emb[b * DE + t + 128];
    __syncthreads();
    float a = bc1[t];
    #pragma unroll 8
    for (int k = 0; k < 256; k++) a += es[k] * Wc1[k * 128 + t];
    float h1 = fmaxf(a, 0.f);
    r0[t] = h1 * Wc2[t * 2 + 0];
    r1[t] = h1 * Wc2[t * 2 + 1];
    __syncthreads();
    for (int off = 64; off > 0; off >>= 1) {
        if (t < off) { r0[t] += r0[t + off]; r1[t] += r1[t + off]; }
        __syncthreads();
    }
    if (t == 0) {
        out[b * 2 + 0] = r0[0] + bc2[0];
        out[b * 2 + 1] = r1[0] + bc2[1];
    }
}

// ---------------- launch ------------------------------------------------------
extern "C" void kernel_launch(void* const* d_in, const int* in_sizes, int n_in,
                              void* d_out, int out_size) {
    (void)in_sizes; (void)n_in; (void)out_size;
    const float* x   = (const float*)d_in[0];
    const int*   ei  = (const int*)d_in[1];       // int32 (JAX x64 disabled)
    const float* We  = (const float*)d_in[2];
    const float* be  = (const float*)d_in[3];
    const float* Wl1 = (const float*)d_in[4];
    const float* bl1 = (const float*)d_in[5];
    const float* Wr1 = (const float*)d_in[6];
    const float* Wl2 = (const float*)d_in[7];
    const float* bl2 = (const float*)d_in[8];
    const float* Wr2 = (const float*)d_in[9];
    // d_in[10..12] (Wlp, blp, Wrp) dead: softmax over a size-1 axis == 1
    const float* Wc1 = (const float*)d_in[13];
    const float* bc1 = (const float*)d_in[14];
    const float* Wc2 = (const float*)d_in[15];
    const float* bc2 = (const float*)d_in[16];
    float* out = (float*)d_out;

    dim3 mma_grid((NN + 127) / 128, 2, BAGS);    // (40, 2, 16)
    dim3 edge_grid((EE + 255) / 256, BAGS);

    k_zero<<<(BAGS * NN + 255) / 256, 256>>>();
    k_prep<<<(P_TOT + 255) / 256, 256>>>(x, ei, We, Wl1, Wr1, Wl2, Wr2);
    k_scan<<<BAGS, 1024>>>();
    k_fill<<<edge_grid, 256>>>(ei);
    // encoder
    k_enc<<<mma_grid, 256>>>(be);
    // layer 1
    k_layer<1, 2><<<mma_grid, 256>>>(bl1);
    k_agg2<false><<<(BAGS * NN) / 8, 256>>>();
    // layer 2 (final combine fuses pooled reduction)
    k_layer<3, 4><<<mma_grid, 256>>>(bl2);
    k_agg2<true><<<(BAGS * NN) / 8, 256>>>();
    // classify
    k_cls<<<BAGS, 128>>>(Wc1, bc1, Wc2, bc2, out);
}

// round 15
// speedup vs baseline: 6.2742x; 6.2742x over previous
#include <cuda_runtime.h>
#include <cuda_fp16.h>
#include <cstdint>

#define BAGS 16
#define NN   5000
#define EE   160000
#define DE   256
#define DIN  128

// ---------------- scratch (device globals) -----------------------------------
__device__ __align__(16) __half g_x [BAGS*NN*DIN];
__device__ __align__(16) __half g_h [BAGS*NN*DE];     // h, later g1
__device__ __align__(16) __half g_u [BAGS*NN*DE];     // u (gathered, fp16)
__device__ __align__(16) __half g_v [BAGS*NN*DE];
__device__ __align__(16) __half g_g2[BAGS*NN*DE];
__device__ float g_emb[BAGS*DE];
// transposed fp16 weights: Wt[n][k] = W[k][n]
__device__ __align__(16) __half g_we[DE*DIN];
__device__ __align__(16) __half g_w1[DE*DE], g_w2[DE*DE], g_w3[DE*DE], g_w4[DE*DE];
// CSR
__device__ int g_deg[BAGS*NN], g_rowptr[BAGS*(NN+1)], g_cursor[BAGS*NN], g_col[BAGS*EE];

// ---------------- helpers -----------------------------------------------------
__device__ __forceinline__ uint32_t smem_u32(const void* p) {
    uint32_t a;
    asm("{ .reg .u64 t; cvta.to.shared.u64 t, %1; cvt.u32.u64 %0, t; }" : "=r"(a) : "l"(p));
    return a;
}
__device__ __forceinline__ uint32_t pack_h2(float v0, float v1) {
    __half2 h = __floats2half2_rn(v0, v1);
    return *reinterpret_cast<uint32_t*>(&h);
}
template <int S> __device__ __forceinline__ const __half* wsel() {
    switch (S) {
        case 0:  return g_we;
        case 1:  return g_w1;
        case 2:  return g_w2;
        case 3:  return g_w3;
        default: return g_w4;
    }
}

// ---------------- prep --------------------------------------------------------
__global__ void k_zero() {
    int i = blockIdx.x * blockDim.x + threadIdx.x;
    if (i < BAGS * NN) g_deg[i] = 0;
    if (i < BAGS * DE) g_emb[i] = 0.f;
}
#define P_DEG (BAGS*EE)
#define P_X   (BAGS*NN*DIN)
#define P_WE  (DE*DIN)
#define P_W4  (4*DE*DE)
#define P_TOT (P_DEG + P_X + P_WE + P_W4)
// one flat kernel: edge-degree histogram + all fp32->fp16 conversions
__global__ void k_prep(const float* __restrict__ x, const int* __restrict__ ei,
                       const float* __restrict__ We, const float* __restrict__ W1,
                       const float* __restrict__ W2, const float* __restrict__ W3,
                       const float* __restrict__ W4) {
    int idx = blockIdx.x * blockDim.x + threadIdx.x;
    if (idx < P_DEG) {
        int b = idx / EE, e = idx - b * EE;
        int dst = ei[(size_t)b * 2 * EE + EE + e];
        if ((unsigned)dst < NN) atomicAdd(&g_deg[b * NN + dst], 1);
        return;
    }
    idx -= P_DEG;
    if (idx < P_X) { g_x[idx] = __float2half_rn(x[idx]); return; }
    idx -= P_X;
    if (idx < P_WE) {
        int n = idx >> 7, k = idx & 127;
        g_we[idx] = __float2half_rn(We[k * DE + n]);
        return;
    }
    idx -= P_WE;
    if (idx < P_W4) {
        int w = idx >> 16, j = idx & 65535;
        const float* W = (w == 0) ? W1 : (w == 1) ? W2 : (w == 2) ? W3 : W4;
        __half* O = (w == 0) ? g_w1 : (w == 1) ? g_w2 : (w == 2) ? g_w3 : g_w4;
        int n = j >> 8, k = j & 255;
        O[j] = __float2half_rn(W[k * DE + n]);
    }
}

// ---------------- CSR scan + fill ---------------------------------------------
__global__ void k_scan() {
    int b = blockIdx.x, t = threadIdx.x;
    __shared__ int sh[1024];
    int carry = 0;
    for (int c = 0; c < 5; c++) {
        int idx = c * 1024 + t;
        int v = (idx < NN) ? g_deg[b * NN + idx] : 0;
        sh[t] = v;
        __syncthreads();
        for (int off = 1; off < 1024; off <<= 1) {
            int add = (t >= off) ? sh[t - off] : 0;
            __syncthreads();
            sh[t] += add;
            __syncthreads();
        }
        int excl = sh[t] - v;
        if (idx < NN) {
            g_rowptr[b * (NN + 1) + idx] = carry + excl;
            g_cursor[b * NN + idx] = carry + excl;
        }
        int tot = sh[1023];
        __syncthreads();
        carry += tot;
    }
    if (t == 0) g_rowptr[b * (NN + 1) + NN] = carry;
}
__global__ void k_fill(const int* __restrict__ ei) {
    int e = blockIdx.x * blockDim.x + threadIdx.x;
    int b = blockIdx.y;
    if (e >= EE) return;
    int src = ei[(size_t)b * 2 * EE + e];
    int dst = ei[(size_t)b * 2 * EE + EE + e];
    if ((unsigned)dst >= NN || (unsigned)src >= NN) return;
    int p = atomicAdd(&g_cursor[b * NN + dst], 1);
    g_col[b * EE + p] = src;
}

// ---------------- GEMM machinery ----------------------------------------------
#define PITCH 80

__device__ __forceinline__ void issue_chunk(
    const __half* __restrict__ Agl, const __half* __restrict__ Bgl,
    int KD, int m0, int kc, char* sA, char* sB, int tid)
{
    #pragma unroll
    for (int v = 0; v < 2; v++) {
        int idx = v * 256 + tid;
        int row = idx >> 2, c16 = idx & 3;
        int gr = m0 + row;
        const void* src = Agl + (size_t)gr * KD + kc + c16 * 8;
        uint32_t dst = smem_u32(sA + row * PITCH + c16 * 16);
        int sz = (gr < NN) ? 16 : 0;
        asm volatile("cp.async.cg.shared.global [%0], [%1], 16, %2;"
                     :: "r"(dst), "l"(src), "r"(sz));
    }
    #pragma unroll
    for (int v = 0; v < 2; v++) {
        int idx = v * 256 + tid;
        int row = idx >> 2, c16 = idx & 3;
        const void* src = Bgl + (size_t)row * KD + kc + c16 * 8;
        uint32_t dst = smem_u32(sB + row * PITCH + c16 * 16);
        asm volatile("cp.async.cg.shared.global [%0], [%1], 16;"
                     :: "r"(dst), "l"(src));
    }
    asm volatile("cp.async.commit_group;");
}

__device__ __forceinline__ void mma_chunk(const char* sA, const char* sB,
                                          int wm, int wn, int lane, float acc[4][4][4]) {
    #pragma unroll
    for (int ks = 0; ks < 2; ks++) {
        uint32_t afr[4][4];
        #pragma unroll
        for (int mi = 0; mi < 4; mi++) {
            uint32_t ad = smem_u32(sA + (wm * 64 + mi * 16 + (lane & 15)) * PITCH
                                      + ks * 32 + (lane >> 4) * 16);
            asm volatile("ldmatrix.sync.aligned.m8n8.x4.shared.b16 {%0,%1,%2,%3}, [%4];"
                         : "=r"(afr[mi][0]), "=r"(afr[mi][1]),
                           "=r"(afr[mi][2]), "=r"(afr[mi][3]) : "r"(ad));
        }
        uint32_t bfr[4][2];
        #pragma unroll
        for (int q = 0; q < 2; q++) {
            int g = lane >> 3;
            uint32_t bd = smem_u32(sB + (wn * 32 + q * 16 + (g >> 1) * 8 + (lane & 7)) * PITCH
                                      + ks * 32 + (g & 1) * 16);
            asm volatile("ldmatrix.sync.aligned.m8n8.x4.shared.b16 {%0,%1,%2,%3}, [%4];"
                         : "=r"(bfr[2 * q][0]), "=r"(bfr[2 * q][1]),
                           "=r"(bfr[2 * q + 1][0]), "=r"(bfr[2 * q + 1][1]) : "r"(bd));
        }
        #pragma unroll
        for (int mi = 0; mi < 4; mi++)
            #pragma unroll
            for (int ni = 0; ni < 4; ni++)
                asm volatile(
                    "mma.sync.aligned.m16n8k16.row.col.f32.f16.f16.f32 "
                    "{%0,%1,%2,%3}, {%4,%5,%6,%7}, {%8,%9}, {%0,%1,%2,%3};"
                    : "+f"(acc[mi][ni][0]), "+f"(acc[mi][ni][1]),
                      "+f"(acc[mi][ni][2]), "+f"(acc[mi][ni][3])
                    : "r"(afr[mi][0]), "r"(afr[mi][1]), "r"(afr[mi][2]), "r"(afr[mi][3]),
                      "r"(bfr[ni][0]), "r"(bfr[ni][1]));
    }
}

// ---------------- encoder: h = relu(x@We + be) -> fp16 ------------------------
__global__ void __launch_bounds__(256, 2) k_enc(const float* __restrict__ bias) {
    __shared__ __align__(16) char smA[2][128 * PITCH];
    __shared__ __align__(16) char smB[2][128 * PITCH];
    const int KD = DIN;
    int tid = threadIdx.x, lane = tid & 31, warp = tid >> 5;
    int wm = warp & 1, wn = warp >> 1;
    int m0 = blockIdx.x * 128, n0 = blockIdx.y * 128, b = blockIdx.z;

    const __half* Ah = g_x + (size_t)b * NN * KD;
    const __half* Bh = g_we + (size_t)n0 * KD;

    const int TOT = KD / 32;
    float acc[4][4][4] = {};
    issue_chunk(Ah, Bh, KD, m0, 0, smA[0], smB[0], tid);
    issue_chunk(Ah, Bh, KD, m0, 32, smA[1], smB[1], tid);
    for (int it = 0; it < TOT; it++) {
        if (it + 1 < TOT) asm volatile("cp.async.wait_group 1;");
        else              asm volatile("cp.async.wait_group 0;");
        __syncthreads();
        mma_chunk(smA[it & 1], smB[it & 1], wm, wn, lane, acc);
        __syncthreads();
        if (it + 2 < TOT)
            issue_chunk(Ah, Bh, KD, m0, (it + 2) * 32, smA[it & 1], smB[it & 1], tid);
    }

    #pragma unroll
    for (int mi = 0; mi < 4; mi++)
        #pragma unroll
        for (int ni = 0; ni < 4; ni++) {
            int r0 = m0 + wm * 64 + mi * 16 + (lane >> 2);
            int c0 = n0 + wn * 32 + ni * 8 + (lane & 3) * 2;
            float b0 = __ldg(&bias[c0]), b1 = __ldg(&bias[c0 + 1]);
            float v00 = fmaxf(acc[mi][ni][0] + b0, 0.f), v01 = fmaxf(acc[mi][ni][1] + b1, 0.f);
            float v10 = fmaxf(acc[mi][ni][2] + b0, 0.f), v11 = fmaxf(acc[mi][ni][3] + b1, 0.f);
            if (r0 < NN)
                *(uint32_t*)&g_h[((size_t)b * NN + r0) * DE + c0] = pack_h2(v00, v01);
            if (r0 + 8 < NN)
                *(uint32_t*)&g_h[((size_t)b * NN + r0 + 8) * DE + c0] = pack_h2(v10, v11);
        }
}

// ---------------- layer GEMM: u = h@Wl (fp16), v = h@Wr + bias (fp16) ---------
template <int WLSEL, int WRSEL>
__global__ void __launch_bounds__(256, 2) k_layer(const float* __restrict__ bias) {
    __shared__ __align__(16) char smA[2][128 * PITCH];
    __shared__ __align__(16) char smB[2][128 * PITCH];
    const int KD = DE;
    int tid = threadIdx.x, lane = tid & 31, warp = tid >> 5;
    int wm = warp & 1, wn = warp >> 1;
    int m0 = blockIdx.x * 128, n0 = blockIdx.y * 128, b = blockIdx.z;

    const __half* Ah = g_h + (size_t)b * NN * KD;
    const __half* WL = wsel<WLSEL>() + (size_t)n0 * KD;
    const __half* WR = wsel<WRSEL>() + (size_t)n0 * KD;

    const int NCH = KD / 32, TOT = 2 * NCH;
    float acc[4][4][4] = {};
    #define BPL(it) ((it) < NCH ? WL : WR)
    issue_chunk(Ah, BPL(0), KD, m0, 0, smA[0], smB[0], tid);
    issue_chunk(Ah, BPL(1), KD, m0, (1 % NCH) * 32, smA[1], smB[1], tid);
    for (int it = 0; it < TOT; it++) {
        if (it + 1 < TOT) asm volatile("cp.async.wait_group 1;");
        else              asm volatile("cp.async.wait_group 0;");
        __syncthreads();
        mma_chunk(smA[it & 1], smB[it & 1], wm, wn, lane, acc);
        __syncthreads();
        if (it + 2 < TOT)
            issue_chunk(Ah, BPL(it + 2), KD, m0, ((it + 2) % NCH) * 32,
                        smA[it & 1], smB[it & 1], tid);
        if (it == NCH - 1) {
            // u complete: write fp16, reset accumulators
            #pragma unroll
            for (int mi = 0; mi < 4; mi++)
                #pragma unroll
                for (int ni = 0; ni < 4; ni++) {
                    int r0 = m0 + wm * 64 + mi * 16 + (lane >> 2);
                    int c0 = n0 + wn * 32 + ni * 8 + (lane & 3) * 2;
                    if (r0 < NN)
                        *(uint32_t*)&g_u[((size_t)b * NN + r0) * DE + c0] =
                            pack_h2(acc[mi][ni][0], acc[mi][ni][1]);
                    if (r0 + 8 < NN)
                        *(uint32_t*)&g_u[((size_t)b * NN + r0 + 8) * DE + c0] =
                            pack_h2(acc[mi][ni][2], acc[mi][ni][3]);
                    acc[mi][ni][0] = acc[mi][ni][1] = acc[mi][ni][2] = acc[mi][ni][3] = 0.f;
                }
        }
    }
    #undef BPL

    // v epilogue (+bias, fp16)
    #pragma unroll
    for (int mi = 0; mi < 4; mi++)
        #pragma unroll
        for (int ni = 0; ni < 4; ni++) {
            int r0 = m0 + wm * 64 + mi * 16 + (lane >> 2);
            int c0 = n0 + wn * 32 + ni * 8 + (lane & 3) * 2;
            float b0 = __ldg(&bias[c0]), b1 = __ldg(&bias[c0 + 1]);
            if (r0 < NN)
                *(uint32_t*)&g_v[((size_t)b * NN + r0) * DE + c0] =
                    pack_h2(acc[mi][ni][0] + b0, acc[mi][ni][1] + b1);
            if (r0 + 8 < NN)
                *(uint32_t*)&g_v[((size_t)b * NN + r0 + 8) * DE + c0] =
                    pack_h2(acc[mi][ni][2] + b0, acc[mi][ni][3] + b1);
        }
}

// ---------------- fused SAGE combine: g = relu(mean_e(U) + V) -----------------
// packed HADD2 f16x2 accumulation: 4 ops per 8 channels, zero conversions.
template <bool FINAL>
__global__ void k_agg2() {
    int w = (blockIdx.x * blockDim.x + threadIdx.x) >> 5;
    int lane = threadIdx.x & 31;
    if (w >= BAGS * NN) return;
    int b = w / NN, i = w - b * NN;
    int r0 = g_rowptr[b * (NN + 1) + i];
    int r1 = g_rowptr[b * (NN + 1) + i + 1];
    const __half* Ub = g_u + (size_t)b * NN * DE;
    const int* colb = g_col + b * EE;
    __half2 a0 = __floats2half2_rn(0.f, 0.f), a1 = a0, a2 = a0, a3 = a0;
    for (int e = r0; e < r1; e++) {
        int s = __ldg(&colb[e]);
        uint4 r = __ldg((const uint4*)(Ub + (size_t)s * DE) + lane);
        a0 = __hadd2(a0, *reinterpret_cast<__half2*>(&r.x));
        a1 = __hadd2(a1, *reinterpret_cast<__half2*>(&r.y));
        a2 = __hadd2(a2, *reinterpret_cast<__half2*>(&r.z));
        a3 = __hadd2(a3, *reinterpret_cast<__half2*>(&r.w));
    }
    int dg = r1 - r0;
    float inv = 1.f / (float)(dg > 1 ? dg : 1);
    size_t base = ((size_t)b * NN + i) * DE + lane * 8;
    uint4 rv = *(const uint4*)(g_v + base);
    float2 f0 = __half22float2(a0), f1 = __half22float2(a1);
    float2 f2 = __half22float2(a2), f3 = __half22float2(a3);
    float2 v0 = __half22float2(*reinterpret_cast<__half2*>(&rv.x));
    float2 v1 = __half22float2(*reinterpret_cast<__half2*>(&rv.y));
    float2 v2 = __half22float2(*reinterpret_cast<__half2*>(&rv.z));
    float2 v3 = __half22float2(*reinterpret_cast<__half2*>(&rv.w));
    float g[8];
    g[0] = fmaxf(f0.x * inv + v0.x, 0.f); g[1] = fmaxf(f0.y * inv + v0.y, 0.f);
    g[2] = fmaxf(f1.x * inv + v1.x, 0.f); g[3] = fmaxf(f1.y * inv + v1.y, 0.f);
    g[4] = fmaxf(f2.x * inv + v2.x, 0.f); g[5] = fmaxf(f2.y * inv + v2.y, 0.f);
    g[6] = fmaxf(f3.x * inv + v3.x, 0.f); g[7] = fmaxf(f3.y * inv + v3.y, 0.f);
    uint32_t hp[4];
    #pragma unroll
    for (int q = 0; q < 4; q++) hp[q] = pack_h2(g[2 * q], g[2 * q + 1]);
    if (!FINAL) *(uint4*)(&g_h[base])  = *(uint4*)hp;
    else        *(uint4*)(&g_g2[base]) = *(uint4*)hp;
}

// ---------------- pooled embedding + classifier -------------------------------
__global__ void k_reduce() {
    int b = blockIdx.y, c = threadIdx.x;
    int i0 = blockIdx.x * 250, i1 = i0 + 250;
    const __half* Gb = g_g2 + (size_t)b * NN * DE;
    float s = 0.f;
    for (int i = i0; i < i1; i++) s += __half2float(Gb[(size_t)i * DE + c]);
    atomicAdd(&g_emb[b * DE + c], s);
}
__global__ void k_cls(const float* __restrict__ Wc1, const float* __restrict__ bc1,
                      const float* __restrict__ Wc2, const float* __restrict__ bc2,
                      float* __restrict__ out) {
    int b = blockIdx.x, t = threadIdx.x;   // 128 threads
    __shared__ float es[256];
    __shared__ float r0[128], r1[128];
    es[t]       = g_emb[b * DE + t];
    es[t + 128] = g_emb[b * DE + t + 128];
    __syncthreads();
    float a = bc1[t];
    #pragma unroll 8
    for (int k = 0; k < 256; k++) a += es[k] * Wc1[k * 128 + t];
    float h1 = fmaxf(a, 0.f);
    r0[t] = h1 * Wc2[t * 2 + 0];
    r1[t] = h1 * Wc2[t * 2 + 1];
    __syncthreads();
    for (int off = 64; off > 0; off >>= 1) {
        if (t < off) { r0[t] += r0[t + off]; r1[t] += r1[t + off]; }
        __syncthreads();
    }
    if (t == 0) {
        out[b * 2 + 0] = r0[0] + bc2[0];
        out[b * 2 + 1] = r1[0] + bc2[1];
    }
}

// ---------------- launch ------------------------------------------------------
extern "C" void kernel_launch(void* const* d_in, const int* in_sizes, int n_in,
                              void* d_out, int out_size) {
    (void)in_sizes; (void)n_in; (void)out_size;
    const float* x   = (const float*)d_in[0];
    const int*   ei  = (const int*)d_in[1];       // int32 (JAX x64 disabled)
    const float* We  = (const float*)d_in[2];
    const float* be  = (const float*)d_in[3];
    const float* Wl1 = (const float*)d_in[4];
    const float* bl1 = (const float*)d_in[5];
    const float* Wr1 = (const float*)d_in[6];
    const float* Wl2 = (const float*)d_in[7];
    const float* bl2 = (const float*)d_in[8];
    const float* Wr2 = (const float*)d_in[9];
    // d_in[10..12] (Wlp, blp, Wrp) dead: softmax over a size-1 axis == 1
    const float* Wc1 = (const float*)d_in[13];
    const float* bc1 = (const float*)d_in[14];
    const float* Wc2 = (const float*)d_in[15];
    const float* bc2 = (const float*)d_in[16];
    float* out = (float*)d_out;

    dim3 mma_grid((NN + 127) / 128, 2, BAGS);    // (40, 2, 16)
    dim3 edge_grid((EE + 255) / 256, BAGS);

    k_zero<<<(BAGS * NN + 255) / 256, 256>>>();
    k_prep<<<(P_TOT + 255) / 256, 256>>>(x, ei, We, Wl1, Wr1, Wl2, Wr2);
    k_scan<<<BAGS, 1024>>>();
    k_fill<<<edge_grid, 256>>>(ei);
    // encoder
    k_enc<<<mma_grid, 256>>>(be);
    // layer 1
    k_layer<1, 2><<<mma_grid, 256>>>(bl1);
    k_agg2<false><<<(BAGS * NN) / 8, 256>>>();
    // layer 2
    k_layer<3, 4><<<mma_grid, 256>>>(bl2);
    k_agg2<true><<<(BAGS * NN) / 8, 256>>>();
    // pool + classify
    k_reduce<<<dim3(20, BAGS), 256>>>();
    k_cls<<<BAGS, 128>>>(Wc1, bc1, Wc2, bc2, out);
}

// round 16
// speedup vs baseline: 6.5005x; 1.0361x over previous
#include <cuda_runtime.h>
#include <cuda_fp16.h>
#include <cstdint>

#define BAGS 16
#define NN   5000
#define EE   160000
#define DE   256
#define DIN  128

// ---------------- scratch (device globals) -----------------------------------
__device__ __align__(16) __half g_x [BAGS*NN*DIN];
__device__ __align__(16) __half g_h [BAGS*NN*DE];     // h, later g1
__device__ __align__(16) __half g_u [BAGS*NN*DE];     // u (gathered, fp16)
__device__ __align__(16) __half g_v [BAGS*NN*DE];
__device__ __align__(16) __half g_g2[BAGS*NN*DE];
__device__ float g_emb[BAGS*DE];
// transposed fp16 weights: Wt[n][k] = W[k][n]
__device__ __align__(16) __half g_we[DE*DIN];
__device__ __align__(16) __half g_w1[DE*DE], g_w2[DE*DE], g_w3[DE*DE], g_w4[DE*DE];
// CSR
__device__ int g_deg[BAGS*NN], g_rowptr[BAGS*(NN+1)], g_cursor[BAGS*NN], g_col[BAGS*EE];

// ---------------- helpers -----------------------------------------------------
__device__ __forceinline__ uint32_t smem_u32(const void* p) {
    uint32_t a;
    asm("{ .reg .u64 t; cvta.to.shared.u64 t, %1; cvt.u32.u64 %0, t; }" : "=r"(a) : "l"(p));
    return a;
}
__device__ __forceinline__ uint32_t pack_h2(float v0, float v1) {
    __half2 h = __floats2half2_rn(v0, v1);
    return *reinterpret_cast<uint32_t*>(&h);
}
template <int S> __device__ __forceinline__ const __half* wsel() {
    switch (S) {
        case 0:  return g_we;
        case 1:  return g_w1;
        case 2:  return g_w2;
        case 3:  return g_w3;
        default: return g_w4;
    }
}

// ---------------- prep --------------------------------------------------------
__global__ void k_zero() {
    int i = blockIdx.x * blockDim.x + threadIdx.x;
    if (i < BAGS * NN) g_deg[i] = 0;
    if (i < BAGS * DE) g_emb[i] = 0.f;
}
#define P_DEG (BAGS*EE)
#define P_X   (BAGS*NN*DIN)
#define P_WE  (DE*DIN)
#define P_W4  (4*DE*DE)
#define P_TOT (P_DEG + P_X + P_WE + P_W4)
// one flat kernel: edge-degree histogram + all fp32->fp16 conversions
__global__ void k_prep(const float* __restrict__ x, const int* __restrict__ ei,
                       const float* __restrict__ We, const float* __restrict__ W1,
                       const float* __restrict__ W2, const float* __restrict__ W3,
                       const float* __restrict__ W4) {
    int idx = blockIdx.x * blockDim.x + threadIdx.x;
    if (idx < P_DEG) {
        int b = idx / EE, e = idx - b * EE;
        int dst = ei[(size_t)b * 2 * EE + EE + e];
        if ((unsigned)dst < NN) atomicAdd(&g_deg[b * NN + dst], 1);
        return;
    }
    idx -= P_DEG;
    if (idx < P_X) { g_x[idx] = __float2half_rn(x[idx]); return; }
    idx -= P_X;
    if (idx < P_WE) {
        int n = idx >> 7, k = idx & 127;
        g_we[idx] = __float2half_rn(We[k * DE + n]);
        return;
    }
    idx -= P_WE;
    if (idx < P_W4) {
        int w = idx >> 16, j = idx & 65535;
        const float* W = (w == 0) ? W1 : (w == 1) ? W2 : (w == 2) ? W3 : W4;
        __half* O = (w == 0) ? g_w1 : (w == 1) ? g_w2 : (w == 2) ? g_w3 : g_w4;
        int n = j >> 8, k = j & 255;
        O[j] = __float2half_rn(W[k * DE + n]);
    }
}

// ---------------- CSR scan + fill ---------------------------------------------
__global__ void k_scan() {
    int b = blockIdx.x, t = threadIdx.x;
    __shared__ int sh[1024];
    int carry = 0;
    for (int c = 0; c < 5; c++) {
        int idx = c * 1024 + t;
        int v = (idx < NN) ? g_deg[b * NN + idx] : 0;
        sh[t] = v;
        __syncthreads();
        for (int off = 1; off < 1024; off <<= 1) {
            int add = (t >= off) ? sh[t - off] : 0;
            __syncthreads();
            sh[t] += add;
            __syncthreads();
        }
        int excl = sh[t] - v;
        if (idx < NN) {
            g_rowptr[b * (NN + 1) + idx] = carry + excl;
            g_cursor[b * NN + idx] = carry + excl;
        }
        int tot = sh[1023];
        __syncthreads();
        carry += tot;
    }
    if (t == 0) g_rowptr[b * (NN + 1) + NN] = carry;
}
__global__ void k_fill(const int* __restrict__ ei) {
    int e = blockIdx.x * blockDim.x + threadIdx.x;
    int b = blockIdx.y;
    if (e >= EE) return;
    int src = ei[(size_t)b * 2 * EE + e];
    int dst = ei[(size_t)b * 2 * EE + EE + e];
    if ((unsigned)dst >= NN || (unsigned)src >= NN) return;
    int p = atomicAdd(&g_cursor[b * NN + dst], 1);
    g_col[b * EE + p] = src;
}

// ---------------- GEMM machinery ----------------------------------------------
#define PITCH 80
#define STG_A  (128 * PITCH)          // 10240 B per stage, A half
#define STG_SZ (2 * STG_A)            // 20480 B per stage (A + B)

__device__ __forceinline__ void issue_chunk(
    const __half* __restrict__ Agl, const __half* __restrict__ Bgl,
    int KD, int m0, int kc, char* sA, char* sB, int tid)
{
    #pragma unroll
    for (int v = 0; v < 2; v++) {
        int idx = v * 256 + tid;
        int row = idx >> 2, c16 = idx & 3;
        int gr = m0 + row;
        const void* src = Agl + (size_t)gr * KD + kc + c16 * 8;
        uint32_t dst = smem_u32(sA + row * PITCH + c16 * 16);
        int sz = (gr < NN) ? 16 : 0;
        asm volatile("cp.async.cg.shared.global [%0], [%1], 16, %2;"
                     :: "r"(dst), "l"(src), "r"(sz));
    }
    #pragma unroll
    for (int v = 0; v < 2; v++) {
        int idx = v * 256 + tid;
        int row = idx >> 2, c16 = idx & 3;
        const void* src = Bgl + (size_t)row * KD + kc + c16 * 8;
        uint32_t dst = smem_u32(sB + row * PITCH + c16 * 16);
        asm volatile("cp.async.cg.shared.global [%0], [%1], 16;"
                     :: "r"(dst), "l"(src));
    }
    asm volatile("cp.async.commit_group;");
}

__device__ __forceinline__ void mma_chunk(const char* sA, const char* sB,
                                          int wm, int wn, int lane, float acc[4][4][4]) {
    #pragma unroll
    for (int ks = 0; ks < 2; ks++) {
        uint32_t afr[4][4];
        #pragma unroll
        for (int mi = 0; mi < 4; mi++) {
            uint32_t ad = smem_u32(sA + (wm * 64 + mi * 16 + (lane & 15)) * PITCH
                                      + ks * 32 + (lane >> 4) * 16);
            asm volatile("ldmatrix.sync.aligned.m8n8.x4.shared.b16 {%0,%1,%2,%3}, [%4];"
                         : "=r"(afr[mi][0]), "=r"(afr[mi][1]),
                           "=r"(afr[mi][2]), "=r"(afr[mi][3]) : "r"(ad));
        }
        uint32_t bfr[4][2];
        #pragma unroll
        for (int q = 0; q < 2; q++) {
            int g = lane >> 3;
            uint32_t bd = smem_u32(sB + (wn * 32 + q * 16 + (g >> 1) * 8 + (lane & 7)) * PITCH
                                      + ks * 32 + (g & 1) * 16);
            asm volatile("ldmatrix.sync.aligned.m8n8.x4.shared.b16 {%0,%1,%2,%3}, [%4];"
                         : "=r"(bfr[2 * q][0]), "=r"(bfr[2 * q][1]),
                           "=r"(bfr[2 * q + 1][0]), "=r"(bfr[2 * q + 1][1]) : "r"(bd));
        }
        #pragma unroll
        for (int mi = 0; mi < 4; mi++)
            #pragma unroll
            for (int ni = 0; ni < 4; ni++)
                asm volatile(
                    "mma.sync.aligned.m16n8k16.row.col.f32.f16.f16.f32 "
                    "{%0,%1,%2,%3}, {%4,%5,%6,%7}, {%8,%9}, {%0,%1,%2,%3};"
                    : "+f"(acc[mi][ni][0]), "+f"(acc[mi][ni][1]),
                      "+f"(acc[mi][ni][2]), "+f"(acc[mi][ni][3])
                    : "r"(afr[mi][0]), "r"(afr[mi][1]), "r"(afr[mi][2]), "r"(afr[mi][3]),
                      "r"(bfr[ni][0]), "r"(bfr[ni][1]));
    }
}

// ---------------- encoder: h = relu(x@We + be) -> fp16 (2-stage, static) ------
__global__ void __launch_bounds__(256, 2) k_enc(const float* __restrict__ bias) {
    __shared__ __align__(16) char smA[2][128 * PITCH];
    __shared__ __align__(16) char smB[2][128 * PITCH];
    const int KD = DIN;
    int tid = threadIdx.x, lane = tid & 31, warp = tid >> 5;
    int wm = warp & 1, wn = warp >> 1;
    int m0 = blockIdx.x * 128, n0 = blockIdx.y * 128, b = blockIdx.z;

    const __half* Ah = g_x + (size_t)b * NN * KD;
    const __half* Bh = g_we + (size_t)n0 * KD;

    const int TOT = KD / 32;
    float acc[4][4][4] = {};
    issue_chunk(Ah, Bh, KD, m0, 0, smA[0], smB[0], tid);
    issue_chunk(Ah, Bh, KD, m0, 32, smA[1], smB[1], tid);
    for (int it = 0; it < TOT; it++) {
        if (it + 1 < TOT) asm volatile("cp.async.wait_group 1;");
        else              asm volatile("cp.async.wait_group 0;");
        __syncthreads();
        mma_chunk(smA[it & 1], smB[it & 1], wm, wn, lane, acc);
        __syncthreads();
        if (it + 2 < TOT)
            issue_chunk(Ah, Bh, KD, m0, (it + 2) * 32, smA[it & 1], smB[it & 1], tid);
    }

    #pragma unroll
    for (int mi = 0; mi < 4; mi++)
        #pragma unroll
        for (int ni = 0; ni < 4; ni++) {
            int r0 = m0 + wm * 64 + mi * 16 + (lane >> 2);
            int c0 = n0 + wn * 32 + ni * 8 + (lane & 3) * 2;
            float b0 = __ldg(&bias[c0]), b1 = __ldg(&bias[c0 + 1]);
            float v00 = fmaxf(acc[mi][ni][0] + b0, 0.f), v01 = fmaxf(acc[mi][ni][1] + b1, 0.f);
            float v10 = fmaxf(acc[mi][ni][2] + b0, 0.f), v11 = fmaxf(acc[mi][ni][3] + b1, 0.f);
            if (r0 < NN)
                *(uint32_t*)&g_h[((size_t)b * NN + r0) * DE + c0] = pack_h2(v00, v01);
            if (r0 + 8 < NN)
                *(uint32_t*)&g_h[((size_t)b * NN + r0 + 8) * DE + c0] = pack_h2(v10, v11);
        }
}

// ---------------- layer GEMM: u = h@Wl, v = h@Wr + bias (fp16) ----------------
// 3-stage single-sync pipeline, dynamic smem (3 x 20480 B).
template <int WLSEL, int WRSEL>
__global__ void __launch_bounds__(256, 2) k_layer(const float* __restrict__ bias) {
    extern __shared__ __align__(16) char sm[];
    const int KD = DE;
    int tid = threadIdx.x, lane = tid & 31, warp = tid >> 5;
    int wm = warp & 1, wn = warp >> 1;
    int m0 = blockIdx.x * 128, n0 = blockIdx.y * 128, b = blockIdx.z;

    const __half* Ah = g_h + (size_t)b * NN * KD;
    const __half* WL = wsel<WLSEL>() + (size_t)n0 * KD;
    const __half* WR = wsel<WRSEL>() + (size_t)n0 * KD;

    const int NCH = KD / 32, TOT = 2 * NCH;
    float acc[4][4][4] = {};
    #define BPL(it) ((it) < NCH ? WL : WR)
    #define SA(s) (sm + (s) * STG_SZ)
    #define SB(s) (sm + (s) * STG_SZ + STG_A)
    issue_chunk(Ah, BPL(0), KD, m0, 0, SA(0), SB(0), tid);
    issue_chunk(Ah, BPL(1), KD, m0, (1 % NCH) * 32, SA(1), SB(1), tid);
    for (int it = 0; it < TOT; it++) {
        // chunk `it` ready (chunk it+1 may remain in flight)
        if (it + 1 < TOT) asm volatile("cp.async.wait_group 1;");
        else              asm volatile("cp.async.wait_group 0;");
        __syncthreads();   // all warps: chunk `it` visible AND mma(it-1) complete
        if (it + 2 < TOT)  // stage (it+2)%3 == (it-1)%3: consumed at it-1, safe
            issue_chunk(Ah, BPL(it + 2), KD, m0, ((it + 2) % NCH) * 32,
                        SA((it + 2) % 3), SB((it + 2) % 3), tid);
        mma_chunk(SA(it % 3), SB(it % 3), wm, wn, lane, acc);
        if (it == NCH - 1) {
            // u complete: write fp16, reset accumulators
            #pragma unroll
            for (int mi = 0; mi < 4; mi++)
                #pragma unroll
                for (int ni = 0; ni < 4; ni++) {
                    int r0 = m0 + wm * 64 + mi * 16 + (lane >> 2);
                    int c0 = n0 + wn * 32 + ni * 8 + (lane & 3) * 2;
                    if (r0 < NN)
                        *(uint32_t*)&g_u[((size_t)b * NN + r0) * DE + c0] =
                            pack_h2(acc[mi][ni][0], acc[mi][ni][1]);
                    if (r0 + 8 < NN)
                        *(uint32_t*)&g_u[((size_t)b * NN + r0 + 8) * DE + c0] =
                            pack_h2(acc[mi][ni][2], acc[mi][ni][3]);
                    acc[mi][ni][0] = acc[mi][ni][1] = acc[mi][ni][2] = acc[mi][ni][3] = 0.f;
                }
        }
    }
    #undef BPL
    #undef SA
    #undef SB

    // v epilogue (+bias, fp16)
    #pragma unroll
    for (int mi = 0; mi < 4; mi++)
        #pragma unroll
        for (int ni = 0; ni < 4; ni++) {
            int r0 = m0 + wm * 64 + mi * 16 + (lane >> 2);
            int c0 = n0 + wn * 32 + ni * 8 + (lane & 3) * 2;
            float b0 = __ldg(&bias[c0]), b1 = __ldg(&bias[c0 + 1]);
            if (r0 < NN)
                *(uint32_t*)&g_v[((size_t)b * NN + r0) * DE + c0] =
                    pack_h2(acc[mi][ni][0] + b0, acc[mi][ni][1] + b1);
            if (r0 + 8 < NN)
                *(uint32_t*)&g_v[((size_t)b * NN + r0 + 8) * DE + c0] =
                    pack_h2(acc[mi][ni][2] + b0, acc[mi][ni][3] + b1);
        }
}

// ---------------- fused SAGE combine: g = relu(mean_e(U) + V) -----------------
// packed HADD2 f16x2 accumulation: 4 ops per 8 channels, zero conversions.
template <bool FINAL>
__global__ void k_agg2() {
    int w = (blockIdx.x * blockDim.x + threadIdx.x) >> 5;
    int lane = threadIdx.x & 31;
    if (w >= BAGS * NN) return;
    int b = w / NN, i = w - b * NN;
    int r0 = g_rowptr[b * (NN + 1) + i];
    int r1 = g_rowptr[b * (NN + 1) + i + 1];
    const __half* Ub = g_u + (size_t)b * NN * DE;
    const int* colb = g_col + b * EE;
    __half2 a0 = __floats2half2_rn(0.f, 0.f), a1 = a0, a2 = a0, a3 = a0;
    for (int e = r0; e < r1; e++) {
        int s = __ldg(&colb[e]);
        uint4 r = __ldg((const uint4*)(Ub + (size_t)s * DE) + lane);
        a0 = __hadd2(a0, *reinterpret_cast<__half2*>(&r.x));
        a1 = __hadd2(a1, *reinterpret_cast<__half2*>(&r.y));
        a2 = __hadd2(a2, *reinterpret_cast<__half2*>(&r.z));
        a3 = __hadd2(a3, *reinterpret_cast<__half2*>(&r.w));
    }
    int dg = r1 - r0;
    float inv = 1.f / (float)(dg > 1 ? dg : 1);
    size_t base = ((size_t)b * NN + i) * DE + lane * 8;
    uint4 rv = *(const uint4*)(g_v + base);
    float2 f0 = __half22float2(a0), f1 = __half22float2(a1);
    float2 f2 = __half22float2(a2), f3 = __half22float2(a3);
    float2 v0 = __half22float2(*reinterpret_cast<__half2*>(&rv.x));
    float2 v1 = __half22float2(*reinterpret_cast<__half2*>(&rv.y));
    float2 v2 = __half22float2(*reinterpret_cast<__half2*>(&rv.z));
    float2 v3 = __half22float2(*reinterpret_cast<__half2*>(&rv.w));
    float g[8];
    g[0] = fmaxf(f0.x * inv + v0.x, 0.f); g[1] = fmaxf(f0.y * inv + v0.y, 0.f);
    g[2] = fmaxf(f1.x * inv + v1.x, 0.f); g[3] = fmaxf(f1.y * inv + v1.y, 0.f);
    g[4] = fmaxf(f2.x * inv + v2.x, 0.f); g[5] = fmaxf(f2.y * inv + v2.y, 0.f);
    g[6] = fmaxf(f3.x * inv + v3.x, 0.f); g[7] = fmaxf(f3.y * inv + v3.y, 0.f);
    uint32_t hp[4];
    #pragma unroll
    for (int q = 0; q < 4; q++) hp[q] = pack_h2(g[2 * q], g[2 * q + 1]);
    if (!FINAL) *(uint4*)(&g_h[base])  = *(uint4*)hp;
    else        *(uint4*)(&g_g2[base]) = *(uint4*)hp;
}

// ---------------- pooled embedding + classifier -------------------------------
__global__ void k_reduce() {
    int b = blockIdx.y, c = threadIdx.x;
    int i0 = blockIdx.x * 250, i1 = i0 + 250;
    const __half* Gb = g_g2 + (size_t)b * NN * DE;
    float s = 0.f;
    for (int i = i0; i < i1; i++) s += __half2float(Gb[(size_t)i * DE + c]);
    atomicAdd(&g_emb[b * DE + c], s);
}
__global__ void k_cls(const float* __restrict__ Wc1, const float* __restrict__ bc1,
                      const float* __restrict__ Wc2, const float* __restrict__ bc2,
                      float* __restrict__ out) {
    int b = blockIdx.x, t = threadIdx.x;   // 128 threads
    __shared__ float es[256];
    __shared__ float r0[128], r1[128];
    es[t]       = g_emb[b * DE + t];
    es[t + 128] = g_emb[b * DE + t + 128];
    __syncthreads();
    float a = bc1[t];
    #pragma unroll 8
    for (int k = 0; k < 256; k++) a += es[k] * Wc1[k * 128 + t];
    float h1 = fmaxf(a, 0.f);
    r0[t] = h1 * Wc2[t * 2 + 0];
    r1[t] = h1 * Wc2[t * 2 + 1];
    __syncthreads();
    for (int off = 64; off > 0; off >>= 1) {
        if (t < off) { r0[t] += r0[t + off]; r1[t] += r1[t + off]; }
        __syncthreads();
    }
    if (t == 0) {
        out[b * 2 + 0] = r0[0] + bc2[0];
        out[b * 2 + 1] = r1[0] + bc2[1];
    }
}

// ---------------- launch ------------------------------------------------------
#define LAYER_SMEM (3 * STG_SZ)   // 61440 bytes

extern "C" void kernel_launch(void* const* d_in, const int* in_sizes, int n_in,
                              void* d_out, int out_size) {
    (void)in_sizes; (void)n_in; (void)out_size;
    const float* x   = (const float*)d_in[0];
    const int*   ei  = (const int*)d_in[1];       // int32 (JAX x64 disabled)
    const float* We  = (const float*)d_in[2];
    const float* be  = (const float*)d_in[3];
    const float* Wl1 = (const float*)d_in[4];
    const float* bl1 = (const float*)d_in[5];
    const float* Wr1 = (const float*)d_in[6];
    const float* Wl2 = (const float*)d_in[7];
    const float* bl2 = (const float*)d_in[8];
    const float* Wr2 = (const float*)d_in[9];
    // d_in[10..12] (Wlp, blp, Wrp) dead: softmax over a size-1 axis == 1
    const float* Wc1 = (const float*)d_in[13];
    const float* bc1 = (const float*)d_in[14];
    const float* Wc2 = (const float*)d_in[15];
    const float* bc2 = (const float*)d_in[16];
    float* out = (float*)d_out;

    cudaFuncSetAttribute(k_layer<1, 2>, cudaFuncAttributeMaxDynamicSharedMemorySize, LAYER_SMEM);
    cudaFuncSetAttribute(k_layer<3, 4>, cudaFuncAttributeMaxDynamicSharedMemorySize, LAYER_SMEM);

    dim3 mma_grid((NN + 127) / 128, 2, BAGS);    // (40, 2, 16)
    dim3 edge_grid((EE + 255) / 256, BAGS);

    k_zero<<<(BAGS * NN + 255) / 256, 256>>>();
    k_prep<<<(P_TOT + 255) / 256, 256>>>(x, ei, We, Wl1, Wr1, Wl2, Wr2);
    k_scan<<<BAGS, 1024>>>();
    k_fill<<<edge_grid, 256>>>(ei);
    // encoder
    k_enc<<<mma_grid, 256>>>(be);
    // layer 1
    k_layer<1, 2><<<mma_grid, 256, LAYER_SMEM>>>(bl1);
    k_agg2<false><<<(BAGS * NN) / 8, 256>>>();
    // layer 2
    k_layer<3, 4><<<mma_grid, 256, LAYER_SMEM>>>(bl2);
    k_agg2<true><<<(BAGS * NN) / 8, 256>>>();
    // pool + classify
    k_reduce<<<dim3(20, BAGS), 256>>>();
    k_cls<<<BAGS, 128>>>(Wc1, bc1, Wc2, bc2, out);
}

// round 17
// speedup vs baseline: 6.6991x; 1.0306x over previous
#include <cuda_runtime.h>
#include <cuda_fp16.h>
#include <cstdint>

#define BAGS 16
#define NN   5000
#define EE   160000
#define DE   256
#define DIN  128

// ---------------- scratch (device globals) -----------------------------------
__device__ __align__(16) __half g_x [BAGS*NN*DIN];
__device__ __align__(16) __half g_h [BAGS*NN*DE];     // h, later g1
__device__ __align__(16) __half g_u [BAGS*NN*DE];     // u (gathered, fp16)
__device__ __align__(16) __half g_v [BAGS*NN*DE];
__device__ __align__(16) __half g_g2[BAGS*NN*DE];
__device__ float g_emb[BAGS*DE];
// transposed fp16 weights: Wt[n][k] = W[k][n]
__device__ __align__(16) __half g_we[DE*DIN];
__device__ __align__(16) __half g_w1[DE*DE], g_w2[DE*DE], g_w3[DE*DE], g_w4[DE*DE];
// CSR
__device__ int g_deg[BAGS*NN], g_rowptr[BAGS*(NN+1)], g_cursor[BAGS*NN], g_col[BAGS*EE];

// ---------------- helpers -----------------------------------------------------
__device__ __forceinline__ uint32_t smem_u32(const void* p) {
    uint32_t a;
    asm("{ .reg .u64 t; cvta.to.shared.u64 t, %1; cvt.u32.u64 %0, t; }" : "=r"(a) : "l"(p));
    return a;
}
__device__ __forceinline__ uint32_t pack_h2(float v0, float v1) {
    __half2 h = __floats2half2_rn(v0, v1);
    return *reinterpret_cast<uint32_t*>(&h);
}
template <int S> __device__ __forceinline__ const __half* wsel() {
    switch (S) {
        case 0:  return g_we;
        case 1:  return g_w1;
        case 2:  return g_w2;
        case 3:  return g_w3;
        default: return g_w4;
    }
}

// ---------------- prep (split for stream overlap) ------------------------------
__global__ void k_zero() {
    int i = blockIdx.x * blockDim.x + threadIdx.x;
    if (i < BAGS * NN) g_deg[i] = 0;
    if (i < BAGS * DE) g_emb[i] = 0.f;
}
// CSR stream: edge-degree histogram
__global__ void k_deg(const int* __restrict__ ei) {
    int idx = blockIdx.x * blockDim.x + threadIdx.x;
    if (idx >= BAGS * EE) return;
    int b = idx / EE, e = idx - b * EE;
    int dst = ei[(size_t)b * 2 * EE + EE + e];
    if ((unsigned)dst < NN) atomicAdd(&g_deg[b * NN + dst], 1);
}
// compute stream: all fp32->fp16 conversions
#define P_X   (BAGS*NN*DIN)
#define P_WE  (DE*DIN)
#define P_W4  (4*DE*DE)
#define P_CVT (P_X + P_WE + P_W4)
__global__ void k_cvt(const float* __restrict__ x,
                      const float* __restrict__ We, const float* __restrict__ W1,
                      const float* __restrict__ W2, const float* __restrict__ W3,
                      const float* __restrict__ W4) {
    int idx = blockIdx.x * blockDim.x + threadIdx.x;
    if (idx < P_X) { g_x[idx] = __float2half_rn(x[idx]); return; }
    idx -= P_X;
    if (idx < P_WE) {
        int n = idx >> 7, k = idx & 127;
        g_we[idx] = __float2half_rn(We[k * DE + n]);
        return;
    }
    idx -= P_WE;
    if (idx < P_W4) {
        int w = idx >> 16, j = idx & 65535;
        const float* W = (w == 0) ? W1 : (w == 1) ? W2 : (w == 2) ? W3 : W4;
        __half* O = (w == 0) ? g_w1 : (w == 1) ? g_w2 : (w == 2) ? g_w3 : g_w4;
        int n = j >> 8, k = j & 255;
        O[j] = __float2half_rn(W[k * DE + n]);
    }
}

// ---------------- CSR scan + fill ---------------------------------------------
__global__ void k_scan() {
    int b = blockIdx.x, t = threadIdx.x;
    __shared__ int sh[1024];
    int carry = 0;
    for (int c = 0; c < 5; c++) {
        int idx = c * 1024 + t;
        int v = (idx < NN) ? g_deg[b * NN + idx] : 0;
        sh[t] = v;
        __syncthreads();
        for (int off = 1; off < 1024; off <<= 1) {
            int add = (t >= off) ? sh[t - off] : 0;
            __syncthreads();
            sh[t] += add;
            __syncthreads();
        }
        int excl = sh[t] - v;
        if (idx < NN) {
            g_rowptr[b * (NN + 1) + idx] = carry + excl;
            g_cursor[b * NN + idx] = carry + excl;
        }
        int tot = sh[1023];
        __syncthreads();
        carry += tot;
    }
    if (t == 0) g_rowptr[b * (NN + 1) + NN] = carry;
}
__global__ void k_fill(const int* __restrict__ ei) {
    int e = blockIdx.x * blockDim.x + threadIdx.x;
    int b = blockIdx.y;
    if (e >= EE) return;
    int src = ei[(size_t)b * 2 * EE + e];
    int dst = ei[(size_t)b * 2 * EE + EE + e];
    if ((unsigned)dst >= NN || (unsigned)src >= NN) return;
    int p = atomicAdd(&g_cursor[b * NN + dst], 1);
    g_col[b * EE + p] = src;
}

// ---------------- GEMM machinery ----------------------------------------------
#define PITCH 80
#define STG_A  (128 * PITCH)          // 10240 B per stage, A half
#define STG_SZ (2 * STG_A)            // 20480 B per stage (A + B)

__device__ __forceinline__ void issue_chunk(
    const __half* __restrict__ Agl, const __half* __restrict__ Bgl,
    int KD, int m0, int kc, char* sA, char* sB, int tid)
{
    #pragma unroll
    for (int v = 0; v < 2; v++) {
        int idx = v * 256 + tid;
        int row = idx >> 2, c16 = idx & 3;
        int gr = m0 + row;
        const void* src = Agl + (size_t)gr * KD + kc + c16 * 8;
        uint32_t dst = smem_u32(sA + row * PITCH + c16 * 16);
        int sz = (gr < NN) ? 16 : 0;
        asm volatile("cp.async.cg.shared.global [%0], [%1], 16, %2;"
                     :: "r"(dst), "l"(src), "r"(sz));
    }
    #pragma unroll
    for (int v = 0; v < 2; v++) {
        int idx = v * 256 + tid;
        int row = idx >> 2, c16 = idx & 3;
        const void* src = Bgl + (size_t)row * KD + kc + c16 * 8;
        uint32_t dst = smem_u32(sB + row * PITCH + c16 * 16);
        asm volatile("cp.async.cg.shared.global [%0], [%1], 16;"
                     :: "r"(dst), "l"(src));
    }
    asm volatile("cp.async.commit_group;");
}

__device__ __forceinline__ void mma_chunk(const char* sA, const char* sB,
                                          int wm, int wn, int lane, float acc[4][4][4]) {
    #pragma unroll
    for (int ks = 0; ks < 2; ks++) {
        uint32_t afr[4][4];
        #pragma unroll
        for (int mi = 0; mi < 4; mi++) {
            uint32_t ad = smem_u32(sA + (wm * 64 + mi * 16 + (lane & 15)) * PITCH
                                      + ks * 32 + (lane >> 4) * 16);
            asm volatile("ldmatrix.sync.aligned.m8n8.x4.shared.b16 {%0,%1,%2,%3}, [%4];"
                         : "=r"(afr[mi][0]), "=r"(afr[mi][1]),
                           "=r"(afr[mi][2]), "=r"(afr[mi][3]) : "r"(ad));
        }
        uint32_t bfr[4][2];
        #pragma unroll
        for (int q = 0; q < 2; q++) {
            int g = lane >> 3;
            uint32_t bd = smem_u32(sB + (wn * 32 + q * 16 + (g >> 1) * 8 + (lane & 7)) * PITCH
                                      + ks * 32 + (g & 1) * 16);
            asm volatile("ldmatrix.sync.aligned.m8n8.x4.shared.b16 {%0,%1,%2,%3}, [%4];"
                         : "=r"(bfr[2 * q][0]), "=r"(bfr[2 * q][1]),
                           "=r"(bfr[2 * q + 1][0]), "=r"(bfr[2 * q + 1][1]) : "r"(bd));
        }
        #pragma unroll
        for (int mi = 0; mi < 4; mi++)
            #pragma unroll
            for (int ni = 0; ni < 4; ni++)
                asm volatile(
                    "mma.sync.aligned.m16n8k16.row.col.f32.f16.f16.f32 "
                    "{%0,%1,%2,%3}, {%4,%5,%6,%7}, {%8,%9}, {%0,%1,%2,%3};"
                    : "+f"(acc[mi][ni][0]), "+f"(acc[mi][ni][1]),
                      "+f"(acc[mi][ni][2]), "+f"(acc[mi][ni][3])
                    : "r"(afr[mi][0]), "r"(afr[mi][1]), "r"(afr[mi][2]), "r"(afr[mi][3]),
                      "r"(bfr[ni][0]), "r"(bfr[ni][1]));
    }
}

// ---------------- encoder: h = relu(x@We + be) -> fp16 (2-stage, static) ------
__global__ void __launch_bounds__(256, 2) k_enc(const float* __restrict__ bias) {
    __shared__ __align__(16) char smA[2][128 * PITCH];
    __shared__ __align__(16) char smB[2][128 * PITCH];
    const int KD = DIN;
    int tid = threadIdx.x, lane = tid & 31, warp = tid >> 5;
    int wm = warp & 1, wn = warp >> 1;
    int m0 = blockIdx.x * 128, n0 = blockIdx.y * 128, b = blockIdx.z;

    const __half* Ah = g_x + (size_t)b * NN * KD;
    const __half* Bh = g_we + (size_t)n0 * KD;

    const int TOT = KD / 32;
    float acc[4][4][4] = {};
    issue_chunk(Ah, Bh, KD, m0, 0, smA[0], smB[0], tid);
    issue_chunk(Ah, Bh, KD, m0, 32, smA[1], smB[1], tid);
    for (int it = 0; it < TOT; it++) {
        if (it + 1 < TOT) asm volatile("cp.async.wait_group 1;");
        else              asm volatile("cp.async.wait_group 0;");
        __syncthreads();
        mma_chunk(smA[it & 1], smB[it & 1], wm, wn, lane, acc);
        __syncthreads();
        if (it + 2 < TOT)
            issue_chunk(Ah, Bh, KD, m0, (it + 2) * 32, smA[it & 1], smB[it & 1], tid);
    }

    #pragma unroll
    for (int mi = 0; mi < 4; mi++)
        #pragma unroll
        for (int ni = 0; ni < 4; ni++) {
            int r0 = m0 + wm * 64 + mi * 16 + (lane >> 2);
            int c0 = n0 + wn * 32 + ni * 8 + (lane & 3) * 2;
            float b0 = __ldg(&bias[c0]), b1 = __ldg(&bias[c0 + 1]);
            float v00 = fmaxf(acc[mi][ni][0] + b0, 0.f), v01 = fmaxf(acc[mi][ni][1] + b1, 0.f);
            float v10 = fmaxf(acc[mi][ni][2] + b0, 0.f), v11 = fmaxf(acc[mi][ni][3] + b1, 0.f);
            if (r0 < NN)
                *(uint32_t*)&g_h[((size_t)b * NN + r0) * DE + c0] = pack_h2(v00, v01);
            if (r0 + 8 < NN)
                *(uint32_t*)&g_h[((size_t)b * NN + r0 + 8) * DE + c0] = pack_h2(v10, v11);
        }
}

// ---------------- layer GEMM: u = h@Wl, v = h@Wr + bias (fp16) ----------------
// 3-stage single-sync pipeline, dynamic smem (3 x 20480 B).
template <int WLSEL, int WRSEL>
__global__ void __launch_bounds__(256, 2) k_layer(const float* __restrict__ bias) {
    extern __shared__ __align__(16) char sm[];
    const int KD = DE;
    int tid = threadIdx.x, lane = tid & 31, warp = tid >> 5;
    int wm = warp & 1, wn = warp >> 1;
    int m0 = blockIdx.x * 128, n0 = blockIdx.y * 128, b = blockIdx.z;

    const __half* Ah = g_h + (size_t)b * NN * KD;
    const __half* WL = wsel<WLSEL>() + (size_t)n0 * KD;
    const __half* WR = wsel<WRSEL>() + (size_t)n0 * KD;

    const int NCH = KD / 32, TOT = 2 * NCH;
    float acc[4][4][4] = {};
    #define BPL(it) ((it) < NCH ? WL : WR)
    #define SA(s) (sm + (s) * STG_SZ)
    #define SB(s) (sm + (s) * STG_SZ + STG_A)
    issue_chunk(Ah, BPL(0), KD, m0, 0, SA(0), SB(0), tid);
    issue_chunk(Ah, BPL(1), KD, m0, (1 % NCH) * 32, SA(1), SB(1), tid);
    for (int it = 0; it < TOT; it++) {
        if (it + 1 < TOT) asm volatile("cp.async.wait_group 1;");
        else              asm volatile("cp.async.wait_group 0;");
        __syncthreads();   // chunk `it` visible AND mma(it-1) complete
        if (it + 2 < TOT)  // stage (it+2)%3 == (it-1)%3: consumed at it-1, safe
            issue_chunk(Ah, BPL(it + 2), KD, m0, ((it + 2) % NCH) * 32,
                        SA((it + 2) % 3), SB((it + 2) % 3), tid);
        mma_chunk(SA(it % 3), SB(it % 3), wm, wn, lane, acc);
        if (it == NCH - 1) {
            // u complete: write fp16, reset accumulators
            #pragma unroll
            for (int mi = 0; mi < 4; mi++)
                #pragma unroll
                for (int ni = 0; ni < 4; ni++) {
                    int r0 = m0 + wm * 64 + mi * 16 + (lane >> 2);
                    int c0 = n0 + wn * 32 + ni * 8 + (lane & 3) * 2;
                    if (r0 < NN)
                        *(uint32_t*)&g_u[((size_t)b * NN + r0) * DE + c0] =
                            pack_h2(acc[mi][ni][0], acc[mi][ni][1]);
                    if (r0 + 8 < NN)
                        *(uint32_t*)&g_u[((size_t)b * NN + r0 + 8) * DE + c0] =
                            pack_h2(acc[mi][ni][2], acc[mi][ni][3]);
                    acc[mi][ni][0] = acc[mi][ni][1] = acc[mi][ni][2] = acc[mi][ni][3] = 0.f;
                }
        }
    }
    #undef BPL
    #undef SA
    #undef SB

    // v epilogue (+bias, fp16)
    #pragma unroll
    for (int mi = 0; mi < 4; mi++)
        #pragma unroll
        for (int ni = 0; ni < 4; ni++) {
            int r0 = m0 + wm * 64 + mi * 16 + (lane >> 2);
            int c0 = n0 + wn * 32 + ni * 8 + (lane & 3) * 2;
            float b0 = __ldg(&bias[c0]), b1 = __ldg(&bias[c0 + 1]);
            if (r0 < NN)
                *(uint32_t*)&g_v[((size_t)b * NN + r0) * DE + c0] =
                    pack_h2(acc[mi][ni][0] + b0, acc[mi][ni][1] + b1);
            if (r0 + 8 < NN)
                *(uint32_t*)&g_v[((size_t)b * NN + r0 + 8) * DE + c0] =
                    pack_h2(acc[mi][ni][2] + b0, acc[mi][ni][3] + b1);
        }
}

// ---------------- fused SAGE combine: g = relu(mean_e(U) + V) -----------------
template <bool FINAL>
__global__ void k_agg2() {
    int w = (blockIdx.x * blockDim.x + threadIdx.x) >> 5;
    int lane = threadIdx.x & 31;
    if (w >= BAGS * NN) return;
    int b = w / NN, i = w - b * NN;
    int r0 = g_rowptr[b * (NN + 1) + i];
    int r1 = g_rowptr[b * (NN + 1) + i + 1];
    const __half* Ub = g_u + (size_t)b * NN * DE;
    const int* colb = g_col + b * EE;
    __half2 a0 = __floats2half2_rn(0.f, 0.f), a1 = a0, a2 = a0, a3 = a0;
    for (int e = r0; e < r1; e++) {
        int s = __ldg(&colb[e]);
        uint4 r = __ldg((const uint4*)(Ub + (size_t)s * DE) + lane);
        a0 = __hadd2(a0, *reinterpret_cast<__half2*>(&r.x));
        a1 = __hadd2(a1, *reinterpret_cast<__half2*>(&r.y));
        a2 = __hadd2(a2, *reinterpret_cast<__half2*>(&r.z));
        a3 = __hadd2(a3, *reinterpret_cast<__half2*>(&r.w));
    }
    int dg = r1 - r0;
    float inv = 1.f / (float)(dg > 1 ? dg : 1);
    size_t base = ((size_t)b * NN + i) * DE + lane * 8;
    uint4 rv = *(const uint4*)(g_v + base);
    float2 f0 = __half22float2(a0), f1 = __half22float2(a1);
    float2 f2 = __half22float2(a2), f3 = __half22float2(a3);
    float2 v0 = __half22float2(*reinterpret_cast<__half2*>(&rv.x));
    float2 v1 = __half22float2(*reinterpret_cast<__half2*>(&rv.y));
    float2 v2 = __half22float2(*reinterpret_cast<__half2*>(&rv.z));
    float2 v3 = __half22float2(*reinterpret_cast<__half2*>(&rv.w));
    float g[8];
    g[0] = fmaxf(f0.x * inv + v0.x, 0.f); g[1] = fmaxf(f0.y * inv + v0.y, 0.f);
    g[2] = fmaxf(f1.x * inv + v1.x, 0.f); g[3] = fmaxf(f1.y * inv + v1.y, 0.f);
    g[4] = fmaxf(f2.x * inv + v2.x, 0.f); g[5] = fmaxf(f2.y * inv + v2.y, 0.f);
    g[6] = fmaxf(f3.x * inv + v3.x, 0.f); g[7] = fmaxf(f3.y * inv + v3.y, 0.f);
    uint32_t hp[4];
    #pragma unroll
    for (int q = 0; q < 4; q++) hp[q] = pack_h2(g[2 * q], g[2 * q + 1]);
    if (!FINAL) *(uint4*)(&g_h[base])  = *(uint4*)hp;
    else        *(uint4*)(&g_g2[base]) = *(uint4*)hp;
}

// ---------------- pooled embedding + classifier -------------------------------
__global__ void k_reduce() {
    int b = blockIdx.y, c = threadIdx.x;
    int i0 = blockIdx.x * 250, i1 = i0 + 250;
    const __half* Gb = g_g2 + (size_t)b * NN * DE;
    float s = 0.f;
    for (int i = i0; i < i1; i++) s += __half2float(Gb[(size_t)i * DE + c]);
    atomicAdd(&g_emb[b * DE + c], s);
}
__global__ void k_cls(const float* __restrict__ Wc1, const float* __restrict__ bc1,
                      const float* __restrict__ Wc2, const float* __restrict__ bc2,
                      float* __restrict__ out) {
    int b = blockIdx.x, t = threadIdx.x;   // 128 threads
    __shared__ float es[256];
    __shared__ float r0[128], r1[128];
    es[t]       = g_emb[b * DE + t];
    es[t + 128] = g_emb[b * DE + t + 128];
    __syncthreads();
    float a = bc1[t];
    #pragma unroll 8
    for (int k = 0; k < 256; k++) a += es[k] * Wc1[k * 128 + t];
    float h1 = fmaxf(a, 0.f);
    r0[t] = h1 * Wc2[t * 2 + 0];
    r1[t] = h1 * Wc2[t * 2 + 1];
    __syncthreads();
    for (int off = 64; off > 0; off >>= 1) {
        if (t < off) { r0[t] += r0[t + off]; r1[t] += r1[t + off]; }
        __syncthreads();
    }
    if (t == 0) {
        out[b * 2 + 0] = r0[0] + bc2[0];
        out[b * 2 + 1] = r1[0] + bc2[1];
    }
}

// ---------------- launch ------------------------------------------------------
#define LAYER_SMEM (3 * STG_SZ)   // 61440 bytes

extern "C" void kernel_launch(void* const* d_in, const int* in_sizes, int n_in,
                              void* d_out, int out_size) {
    (void)in_sizes; (void)n_in; (void)out_size;
    const float* x   = (const float*)d_in[0];
    const int*   ei  = (const int*)d_in[1];       // int32 (JAX x64 disabled)
    const float* We  = (const float*)d_in[2];
    const float* be  = (const float*)d_in[3];
    const float* Wl1 = (const float*)d_in[4];
    const float* bl1 = (const float*)d_in[5];
    const float* Wr1 = (const float*)d_in[6];
    const float* Wl2 = (const float*)d_in[7];
    const float* bl2 = (const float*)d_in[8];
    const float* Wr2 = (const float*)d_in[9];
    // d_in[10..12] (Wlp, blp, Wrp) dead: softmax over a size-1 axis == 1
    const float* Wc1 = (const float*)d_in[13];
    const float* bc1 = (const float*)d_in[14];
    const float* Wc2 = (const float*)d_in[15];
    const float* bc2 = (const float*)d_in[16];
    float* out = (float*)d_out;

    // persistent side stream + fork/join events (host resources, created once;
    // captured work is identical on every call)
    static cudaStream_t s_csr = nullptr;
    static cudaEvent_t  e_fork = nullptr, e_join = nullptr;
    if (!s_csr) {
        cudaStreamCreateWithFlags(&s_csr, cudaStreamNonBlocking);
        cudaEventCreateWithFlags(&e_fork, cudaEventDisableTiming);
        cudaEventCreateWithFlags(&e_join, cudaEventDisableTiming);
    }

    cudaFuncSetAttribute(k_layer<1, 2>, cudaFuncAttributeMaxDynamicSharedMemorySize, LAYER_SMEM);
    cudaFuncSetAttribute(k_layer<3, 4>, cudaFuncAttributeMaxDynamicSharedMemorySize, LAYER_SMEM);

    dim3 mma_grid((NN + 127) / 128, 2, BAGS);    // (40, 2, 16)
    dim3 edge_grid((EE + 255) / 256, BAGS);

    // ---- fork: CSR chain on side stream, compute chain on origin stream ----
    cudaEventRecord(e_fork, 0);
    cudaStreamWaitEvent(s_csr, e_fork, 0);

    // CSR chain (side stream): zero -> deg -> scan -> fill
    k_zero<<<(BAGS * NN + 255) / 256, 256, 0, s_csr>>>();
    k_deg<<<(BAGS * EE + 255) / 256, 256, 0, s_csr>>>(ei);
    k_scan<<<BAGS, 1024, 0, s_csr>>>();
    k_fill<<<edge_grid, 256, 0, s_csr>>>(ei);
    cudaEventRecord(e_join, s_csr);

    // compute chain (origin stream): cvt -> enc -> layer1
    k_cvt<<<(P_CVT + 255) / 256, 256>>>(x, We, Wl1, Wr1, Wl2, Wr2);
    k_enc<<<mma_grid, 256>>>(be);
    k_layer<1, 2><<<mma_grid, 256, LAYER_SMEM>>>(bl1);

    // ---- join: gather needs CSR ----
    cudaStreamWaitEvent(0, e_join, 0);
    k_agg2<false><<<(BAGS * NN) / 8, 256>>>();
    // layer 2
    k_layer<3, 4><<<mma_grid, 256, LAYER_SMEM>>>(bl2);
    k_agg2<true><<<(BAGS * NN) / 8, 256>>>();
    // pool + classify
    k_reduce<<<dim3(20, BAGS), 256>>>();
    k_cls<<<BAGS, 128>>>(Wc1, bc1, Wc2, bc2, out);
}